// round 1
// baseline (speedup 1.0000x reference)
#include <cuda_runtime.h>
#include <cuda_bf16.h>

// Problem constants (shapes fixed by the dataset)
#define D        64
#define K        512
#define TPB      512

// dynamic smem: K*D codeword floats + K half-csq floats
#define SMEM_BYTES ((K * D + K) * (int)sizeof(float))

__device__ float g_loss_accum;

__global__ void vq_init_kernel() {
    g_loss_accum = 0.0f;
}

__global__ __launch_bounds__(TPB) void vq_main_kernel(
    const float* __restrict__ inputs,     // (N, D)
    const float* __restrict__ codewords,  // (K, D)
    float* __restrict__ out,              // [N*D quantized | N indices | 1 loss]
    int N)
{
    extern __shared__ float smem[];
    float* sc        = smem;           // K*D codewords
    float* s_halfcsq = smem + K * D;   // K values of 0.5*||c||^2

    // --- stage codewords into smem (coalesced float4) ---
    {
        const float4* cw4 = reinterpret_cast<const float4*>(codewords);
        float4* sc4 = reinterpret_cast<float4*>(sc);
        #pragma unroll 4
        for (int i = threadIdx.x; i < K * D / 4; i += TPB) sc4[i] = cw4[i];
    }
    __syncthreads();

    // --- precompute 0.5 * ||c_k||^2 (one codeword per thread, K==TPB) ---
    {
        int k = threadIdx.x;
        const float* c = sc + k * D;
        float s = 0.0f;
        #pragma unroll
        for (int d = 0; d < D; d++) s = fmaf(c[d], c[d], s);
        s_halfcsq[k] = 0.5f * s;
    }
    __syncthreads();

    const int i = blockIdx.x * TPB + threadIdx.x;   // vector index (grid sized exactly)

    // --- load this thread's input vector into registers ---
    float4 x[D / 4];
    float xsq = 0.0f;
    {
        const float4* xin = reinterpret_cast<const float4*>(inputs + (size_t)i * D);
        #pragma unroll
        for (int j = 0; j < D / 4; j++) {
            x[j] = xin[j];
            xsq = fmaf(x[j].x, x[j].x, xsq);
            xsq = fmaf(x[j].y, x[j].y, xsq);
            xsq = fmaf(x[j].z, x[j].z, xsq);
            xsq = fmaf(x[j].w, x[j].w, xsq);
        }
    }

    // --- scan all K codewords: score_k = 0.5*||c||^2 - x.c  (argmin == argmin dist) ---
    float best = 3.402823466e38f;
    int bidx = 0;
    #pragma unroll 2
    for (int k = 0; k < K; k++) {
        const float4* c4 = reinterpret_cast<const float4*>(sc + k * D);
        float a0 = 0.f, a1 = 0.f, a2 = 0.f, a3 = 0.f;
        #pragma unroll
        for (int j = 0; j < D / 4; j++) {
            float4 cv = c4[j];           // broadcast LDS.128 (all lanes same addr)
            a0 = fmaf(x[j].x, cv.x, a0);
            a1 = fmaf(x[j].y, cv.y, a1);
            a2 = fmaf(x[j].z, cv.z, a2);
            a3 = fmaf(x[j].w, cv.w, a3);
        }
        float score = s_halfcsq[k] - ((a0 + a1) + (a2 + a3));
        if (score < best) { best = score; bidx = k; }
    }

    // --- write quantized vector (gather winning codeword from smem) ---
    {
        float4* q = reinterpret_cast<float4*>(out + (size_t)i * D);
        const float4* cb = reinterpret_cast<const float4*>(sc + bidx * D);
        #pragma unroll
        for (int j = 0; j < D / 4; j++) q[j] = cb[j];
    }

    // --- write index (as float, concatenated-output convention) ---
    out[(size_t)N * D + i] = (float)bidx;

    // --- commitment-loss partial: min dist = xsq + 2*best ---
    float part = fmaf(2.0f, best, xsq);
    #pragma unroll
    for (int o = 16; o > 0; o >>= 1)
        part += __shfl_xor_sync(0xffffffffu, part, o);

    __shared__ float wsum[TPB / 32];
    if ((threadIdx.x & 31) == 0) wsum[threadIdx.x >> 5] = part;
    __syncthreads();
    if (threadIdx.x == 0) {
        float s = 0.0f;
        #pragma unroll
        for (int w = 0; w < TPB / 32; w++) s += wsum[w];
        atomicAdd(&g_loss_accum, s);
    }
}

__global__ void vq_finish_kernel(float* __restrict__ out, int N) {
    out[(size_t)N * D + N] = 0.25f * g_loss_accum / (float)((size_t)N * D);
}

extern "C" void kernel_launch(void* const* d_in, const int* in_sizes, int n_in,
                              void* d_out, int out_size) {
    const float* inputs    = (const float*)d_in[0];
    const float* codewords = (const float*)d_in[1];
    float* out = (float*)d_out;

    const int N = in_sizes[0] / D;   // 262144

    cudaFuncSetAttribute(vq_main_kernel,
                         cudaFuncAttributeMaxDynamicSharedMemorySize, SMEM_BYTES);

    vq_init_kernel<<<1, 1>>>();
    vq_main_kernel<<<N / TPB, TPB, SMEM_BYTES>>>(inputs, codewords, out, N);
    vq_finish_kernel<<<1, 1>>>(out, N);
}

// round 3
// speedup vs baseline: 2.3280x; 2.3280x over previous
#include <cuda_runtime.h>
#include <cuda_bf16.h>
#include <cstdint>

#define D      64
#define KCW    512
#define NROWS  262144
#define TILE_M 128
#define NTILES (NROWS / TILE_M)

#define BSTRIDE   144          // 64 bf16 = 128B data + 16B pad -> conflict-free frag LDS
#define CHI_OFF   0            // 512*144 = 73728
#define CLO_OFF   73728
#define A0_OFF    147456       // 128*144*2 (hi+lo) = 36864 per buffer
#define A1_OFF    184320
#define ALO_DELTA 18432
#define HCSQ_OFF  221184       // 512 floats
#define SM_TOTAL  223232
#define THRESH    2e-3f

// ---------------- device scratch ----------------
__device__ __nv_bfloat16 g_xhi[NROWS * D];
__device__ __nv_bfloat16 g_xlo[NROWS * D];
__device__ float         g_xsq[NROWS];
__device__ __nv_bfloat16 g_chi[KCW * D];
__device__ __nv_bfloat16 g_clo[KCW * D];
__device__ float         g_hcsq[KCW];
__device__ float         g_loss;

// ---------------- helpers ----------------
__device__ __forceinline__ uint32_t smem_u32(const void* p) {
    uint32_t a;
    asm("{ .reg .u64 t; cvta.to.shared.u64 t, %1; cvt.u32.u64 %0, t; }" : "=r"(a) : "l"(p));
    return a;
}
__device__ __forceinline__ void cp16(uint32_t dst, const void* src) {
    asm volatile("cp.async.cg.shared.global [%0], [%1], 16;" :: "r"(dst), "l"(src) : "memory");
}
__device__ __forceinline__ void cp_commit() { asm volatile("cp.async.commit_group;" ::: "memory"); }
__device__ __forceinline__ void cp_wait1()  { asm volatile("cp.async.wait_group 1;"  ::: "memory"); }

__device__ __forceinline__ void mma_bf16(float& c0, float& c1, float& c2, float& c3,
                                         uint32_t a0, uint32_t a1, uint32_t a2, uint32_t a3,
                                         uint32_t b0, uint32_t b1) {
    asm volatile("mma.sync.aligned.m16n8k16.row.col.f32.bf16.bf16.f32 "
                 "{%0,%1,%2,%3}, {%4,%5,%6,%7}, {%8,%9}, {%0,%1,%2,%3};"
                 : "+f"(c0), "+f"(c1), "+f"(c2), "+f"(c3)
                 : "r"(a0), "r"(a1), "r"(a2), "r"(a3), "r"(b0), "r"(b1));
}

__device__ __forceinline__ void upd2(float v, int k, float& s1, int& i1, float& s2, int& i2) {
    if (v < s1)      { s2 = s1; i2 = i1; s1 = v; i1 = k; }
    else if (v < s2) { s2 = v; i2 = k; }
}

// ---------------- prep kernels ----------------
__global__ __launch_bounds__(256) void prep_inputs_kernel(const float* __restrict__ x) {
    unsigned i = blockIdx.x * 256u + threadIdx.x;   // one float4 per thread
    float4 v = reinterpret_cast<const float4*>(x)[i];
    __nv_bfloat16 h0 = __float2bfloat16(v.x), h1 = __float2bfloat16(v.y);
    __nv_bfloat16 h2 = __float2bfloat16(v.z), h3 = __float2bfloat16(v.w);
    __nv_bfloat162 ph0; ph0.x = h0; ph0.y = h1;
    __nv_bfloat162 ph1; ph1.x = h2; ph1.y = h3;
    reinterpret_cast<__nv_bfloat162*>(g_xhi)[2u * i]     = ph0;
    reinterpret_cast<__nv_bfloat162*>(g_xhi)[2u * i + 1] = ph1;
    __nv_bfloat162 pl0, pl1;
    pl0.x = __float2bfloat16(v.x - __bfloat162float(h0));
    pl0.y = __float2bfloat16(v.y - __bfloat162float(h1));
    pl1.x = __float2bfloat16(v.z - __bfloat162float(h2));
    pl1.y = __float2bfloat16(v.w - __bfloat162float(h3));
    reinterpret_cast<__nv_bfloat162*>(g_xlo)[2u * i]     = pl0;
    reinterpret_cast<__nv_bfloat162*>(g_xlo)[2u * i + 1] = pl1;
    float p = v.x * v.x + v.y * v.y + v.z * v.z + v.w * v.w;
    p += __shfl_xor_sync(0xffffffffu, p, 1);
    p += __shfl_xor_sync(0xffffffffu, p, 2);
    p += __shfl_xor_sync(0xffffffffu, p, 4);
    p += __shfl_xor_sync(0xffffffffu, p, 8);
    if ((threadIdx.x & 15) == 0) g_xsq[i >> 4] = p;
}

__global__ __launch_bounds__(256) void prep_codewords_kernel(const float* __restrict__ cw) {
    unsigned i = blockIdx.x * 256u + threadIdx.x;
    float4 v = reinterpret_cast<const float4*>(cw)[i];
    __nv_bfloat16 h0 = __float2bfloat16(v.x), h1 = __float2bfloat16(v.y);
    __nv_bfloat16 h2 = __float2bfloat16(v.z), h3 = __float2bfloat16(v.w);
    __nv_bfloat162 ph0; ph0.x = h0; ph0.y = h1;
    __nv_bfloat162 ph1; ph1.x = h2; ph1.y = h3;
    reinterpret_cast<__nv_bfloat162*>(g_chi)[2u * i]     = ph0;
    reinterpret_cast<__nv_bfloat162*>(g_chi)[2u * i + 1] = ph1;
    __nv_bfloat162 pl0, pl1;
    pl0.x = __float2bfloat16(v.x - __bfloat162float(h0));
    pl0.y = __float2bfloat16(v.y - __bfloat162float(h1));
    pl1.x = __float2bfloat16(v.z - __bfloat162float(h2));
    pl1.y = __float2bfloat16(v.w - __bfloat162float(h3));
    reinterpret_cast<__nv_bfloat162*>(g_clo)[2u * i]     = pl0;
    reinterpret_cast<__nv_bfloat162*>(g_clo)[2u * i + 1] = pl1;
    float p = v.x * v.x + v.y * v.y + v.z * v.z + v.w * v.w;
    p += __shfl_xor_sync(0xffffffffu, p, 1);
    p += __shfl_xor_sync(0xffffffffu, p, 2);
    p += __shfl_xor_sync(0xffffffffu, p, 4);
    p += __shfl_xor_sync(0xffffffffu, p, 8);
    if ((threadIdx.x & 15) == 0) g_hcsq[i >> 4] = 0.5f * p;
    if (blockIdx.x == 0 && threadIdx.x == 0) g_loss = 0.0f;
}

// ---------------- main persistent kernel ----------------
__global__ __launch_bounds__(256, 1) void vq_main_kernel(
    const float* __restrict__ inputs,
    const float* __restrict__ cwf,
    float* __restrict__ out,
    int grid)
{
    extern __shared__ char sm[];
    const int tid = threadIdx.x, wid = tid >> 5, lane = tid & 31;
    const int g = lane >> 2, q = lane & 3;
    const uint32_t sb = smem_u32(sm);

    // prologue group G0: codebook (hi/lo) + hcsq + first A tile
    for (int i = tid; i < KCW * 8; i += 256) {
        int r = i >> 3, j = i & 7;
        cp16(sb + CHI_OFF + r * BSTRIDE + j * 16, g_chi + r * 64 + j * 8);
        cp16(sb + CLO_OFF + r * BSTRIDE + j * 16, g_clo + r * 64 + j * 8);
    }
    if (tid < 128) cp16(sb + HCSQ_OFF + tid * 16, g_hcsq + tid * 4);
    {
        int t0 = blockIdx.x;
        for (int i = tid; i < TILE_M * 8; i += 256) {
            int r = i >> 3, j = i & 7;
            cp16(sb + A0_OFF + r * BSTRIDE + j * 16,             g_xhi + (size_t)(t0 * TILE_M + r) * 64 + j * 8);
            cp16(sb + A0_OFF + ALO_DELTA + r * BSTRIDE + j * 16, g_xlo + (size_t)(t0 * TILE_M + r) * 64 + j * 8);
        }
    }
    cp_commit();

    int lt = 0;
    for (int t = blockIdx.x; t < NTILES; t += grid, lt++) {
        __syncthreads();   // previous compute fully done before overwriting its buffer
        int tn = t + grid;
        if (tn < NTILES) {
            uint32_t ab = sb + (((lt + 1) & 1) ? A1_OFF : A0_OFF);
            for (int i = tid; i < TILE_M * 8; i += 256) {
                int r = i >> 3, j = i & 7;
                cp16(ab + r * BSTRIDE + j * 16,             g_xhi + (size_t)(tn * TILE_M + r) * 64 + j * 8);
                cp16(ab + ALO_DELTA + r * BSTRIDE + j * 16, g_xlo + (size_t)(tn * TILE_M + r) * 64 + j * 8);
            }
        }
        cp_commit();
        cp_wait1();        // current tile (and codebook on iter 0) resident
        __syncthreads();

        const char* abase = sm + ((lt & 1) ? A1_OFF : A0_OFF);

        // ---- A fragments (held across all N-chunks) ----
        uint32_t ah[4][4], al[4][4];
        {
            const int rA = wid * 16 + g, rB = rA + 8;
            const char* pA = abase + rA * BSTRIDE + q * 4;
            const char* pB = abase + rB * BSTRIDE + q * 4;
            #pragma unroll
            for (int ks = 0; ks < 4; ks++) {
                ah[ks][0] = *(const uint32_t*)(pA + ks * 32);
                ah[ks][1] = *(const uint32_t*)(pB + ks * 32);
                ah[ks][2] = *(const uint32_t*)(pA + ks * 32 + 16);
                ah[ks][3] = *(const uint32_t*)(pB + ks * 32 + 16);
                al[ks][0] = *(const uint32_t*)(pA + ALO_DELTA + ks * 32);
                al[ks][1] = *(const uint32_t*)(pB + ALO_DELTA + ks * 32);
                al[ks][2] = *(const uint32_t*)(pA + ALO_DELTA + ks * 32 + 16);
                al[ks][3] = *(const uint32_t*)(pB + ALO_DELTA + ks * 32 + 16);
            }
        }

        float s1a = 3.4e38f, s2a = 3.4e38f, s1b = 3.4e38f, s2b = 3.4e38f;
        int   i1a = 0, i2a = 0, i1b = 0, i2b = 0;

        const char* bh_base = sm + CHI_OFF + g * BSTRIDE + q * 4;
        const char* hc_base = sm + HCSQ_OFF + q * 8;

        for (int cn = 0; cn < 4; cn++) {               // N-chunks of 128 codewords
            float acc[16][4];
            #pragma unroll
            for (int nt = 0; nt < 16; nt++) {
                acc[nt][0] = 0.f; acc[nt][1] = 0.f; acc[nt][2] = 0.f; acc[nt][3] = 0.f;
            }
            const char* bcn = bh_base + cn * 128 * BSTRIDE;
            #pragma unroll
            for (int ks = 0; ks < 4; ks++) {
                #pragma unroll
                for (int ng = 0; ng < 4; ng++) {
                    uint32_t bh0[4], bh1[4], bl0[4], bl1[4];
                    #pragma unroll
                    for (int u = 0; u < 4; u++) {
                        const char* p = bcn + (ng * 4 + u) * 8 * BSTRIDE + ks * 32;
                        bh0[u] = *(const uint32_t*)p;
                        bh1[u] = *(const uint32_t*)(p + 16);
                        bl0[u] = *(const uint32_t*)(p + CLO_OFF);
                        bl1[u] = *(const uint32_t*)(p + CLO_OFF + 16);
                    }
                    // 4-way nt interleave keeps same-accumulator HMMAs >= 4 apart
                    #pragma unroll
                    for (int u = 0; u < 4; u++) { int nt = ng * 4 + u;
                        mma_bf16(acc[nt][0], acc[nt][1], acc[nt][2], acc[nt][3],
                                 ah[ks][0], ah[ks][1], ah[ks][2], ah[ks][3], bh0[u], bh1[u]); }
                    #pragma unroll
                    for (int u = 0; u < 4; u++) { int nt = ng * 4 + u;
                        mma_bf16(acc[nt][0], acc[nt][1], acc[nt][2], acc[nt][3],
                                 al[ks][0], al[ks][1], al[ks][2], al[ks][3], bh0[u], bh1[u]); }
                    #pragma unroll
                    for (int u = 0; u < 4; u++) { int nt = ng * 4 + u;
                        mma_bf16(acc[nt][0], acc[nt][1], acc[nt][2], acc[nt][3],
                                 ah[ks][0], ah[ks][1], ah[ks][2], ah[ks][3], bl0[u], bl1[u]); }
                }
            }
            // chunk epilogue: scores -> per-lane top-2 (rows g and g+8 separately)
            #pragma unroll
            for (int nt = 0; nt < 16; nt++) {
                float2 hc = *(const float2*)(hc_base + (cn * 128 + nt * 8) * 4);
                int col = cn * 128 + nt * 8 + 2 * q;
                float v0 = hc.x - acc[nt][0];
                float v1 = hc.y - acc[nt][1];
                float v2 = hc.x - acc[nt][2];
                float v3 = hc.y - acc[nt][3];
                upd2(v0, col,     s1a, i1a, s2a, i2a);
                upd2(v1, col + 1, s1a, i1a, s2a, i2a);
                upd2(v2, col,     s1b, i1b, s2b, i2b);
                upd2(v3, col + 1, s1b, i1b, s2b, i2b);
            }
        }

        // ---- merge top-2 across the 4 lanes of each row-group ----
        #pragma unroll
        for (int off = 1; off <= 2; off <<= 1) {
            float os1 = __shfl_xor_sync(0xffffffffu, s1a, off);
            int   oi1 = __shfl_xor_sync(0xffffffffu, i1a, off);
            float os2 = __shfl_xor_sync(0xffffffffu, s2a, off);
            int   oi2 = __shfl_xor_sync(0xffffffffu, i2a, off);
            float cs; int ci;
            if (os1 < s1a) { cs = s1a; ci = i1a; s1a = os1; i1a = oi1; } else { cs = os1; ci = oi1; }
            if (cs  < s2a) { s2a = cs;  i2a = ci; }
            if (os2 < s2a) { s2a = os2; i2a = oi2; }

            os1 = __shfl_xor_sync(0xffffffffu, s1b, off);
            oi1 = __shfl_xor_sync(0xffffffffu, i1b, off);
            os2 = __shfl_xor_sync(0xffffffffu, s2b, off);
            oi2 = __shfl_xor_sync(0xffffffffu, i2b, off);
            if (os1 < s1b) { cs = s1b; ci = i1b; s1b = os1; i1b = oi1; } else { cs = os1; ci = oi1; }
            if (cs  < s2b) { s2b = cs;  i2b = ci; }
            if (os2 < s2b) { s2b = os2; i2b = oi2; }
        }

        const int rowA = t * TILE_M + wid * 16 + g;
        const int rowB = rowA + 8;

        float dist = 0.0f;
        if (q < 2) {
            float s1 = q ? s1b : s1a;
            float s2 = q ? s2b : s2a;
            int   j1 = q ? i1b : i1a;
            int   j2 = q ? i2b : i2a;
            const int myrow = q ? rowB : rowA;
            if (s2 - s1 < THRESH) {
                // exact fp32 refinement of the top-2 candidates
                const float4* x  = (const float4*)(inputs + (size_t)myrow * D);
                const float4* p1 = (const float4*)(cwf + (size_t)j1 * D);
                const float4* p2 = (const float4*)(cwf + (size_t)j2 * D);
                float d1 = 0.f, d2 = 0.f;
                #pragma unroll
                for (int j = 0; j < 16; j++) {
                    float4 xv = x[j], c1 = p1[j], c2 = p2[j];
                    float e;
                    e = xv.x - c1.x; d1 = fmaf(e, e, d1);
                    e = xv.y - c1.y; d1 = fmaf(e, e, d1);
                    e = xv.z - c1.z; d1 = fmaf(e, e, d1);
                    e = xv.w - c1.w; d1 = fmaf(e, e, d1);
                    e = xv.x - c2.x; d2 = fmaf(e, e, d2);
                    e = xv.y - c2.y; d2 = fmaf(e, e, d2);
                    e = xv.z - c2.z; d2 = fmaf(e, e, d2);
                    e = xv.w - c2.w; d2 = fmaf(e, e, d2);
                }
                if (d2 < d1 || (d2 == d1 && j2 < j1)) { d1 = d2; j1 = j2; }
                dist = d1;
            } else {
                dist = fmaf(2.0f, s1, g_xsq[myrow]);
            }
            out[(size_t)NROWS * D + myrow] = (float)j1;
            if (q == 0) i1a = j1; else i1b = j1;  // carry refined winner
        }

        // broadcast winners to quad, gather exact fp32 codewords cooperatively
        const int bl = lane & ~3;
        const int bA = __shfl_sync(0xffffffffu, i1a, bl);
        const int bB = __shfl_sync(0xffffffffu, i1b, bl + 1);
        {
            const float4* cA = (const float4*)(cwf + (size_t)bA * D);
            const float4* cB = (const float4*)(cwf + (size_t)bB * D);
            float4* oA = (float4*)(out + (size_t)rowA * D);
            float4* oB = (float4*)(out + (size_t)rowB * D);
            #pragma unroll
            for (int j = 0; j < 4; j++) {
                oA[q * 4 + j] = cA[q * 4 + j];
                oB[q * 4 + j] = cB[q * 4 + j];
            }
        }

        // loss partial (lanes q>=2 contribute 0)
        #pragma unroll
        for (int off = 16; off; off >>= 1) dist += __shfl_xor_sync(0xffffffffu, dist, off);
        if (lane == 0) atomicAdd(&g_loss, dist);
    }
}

__global__ void vq_finish_kernel(float* __restrict__ out) {
    out[(size_t)NROWS * D + NROWS] = 0.25f * g_loss / (float)((size_t)NROWS * D);
}

// ---------------- launch ----------------
extern "C" void kernel_launch(void* const* d_in, const int* in_sizes, int n_in,
                              void* d_out, int out_size) {
    const float* inputs    = (const float*)d_in[0];
    const float* codewords = (const float*)d_in[1];
    float* out = (float*)d_out;

    int sms = 148;
    cudaDeviceGetAttribute(&sms, cudaDevAttrMultiProcessorCount, 0);
    if (sms > NTILES) sms = NTILES;

    cudaFuncSetAttribute(vq_main_kernel,
                         cudaFuncAttributeMaxDynamicSharedMemorySize, SM_TOTAL);

    prep_inputs_kernel<<<NROWS * D / 4 / 256, 256>>>(inputs);
    prep_codewords_kernel<<<KCW * D / 4 / 256, 256>>>(codewords);
    vq_main_kernel<<<sms, 256, SM_TOTAL>>>(inputs, codewords, out, sms);
    vq_finish_kernel<<<1, 1>>>(out);
}

// round 4
// speedup vs baseline: 2.4969x; 1.0725x over previous
#include <cuda_runtime.h>
#include <cuda_fp16.h>
#include <cstdint>

#define D       64
#define KCW     512
#define NROWS   262144
#define TILE_M  128
#define NTILES  (NROWS / TILE_M)

#define BSTRIDE  144            // 64 fp16 = 128B + 16B pad -> conflict-free LDS
#define CB_OFF   0              // 512*144 = 73728
#define HCSQ_OFF 73728          // 512 f32  = 2048
#define XS0_OFF  75776          // fp32 staging, 128*256B = 32768
#define XS1_OFF  108544
#define A0_OFF   141312         // fp16 tile, 128*144 = 18432
#define A1_OFF   159744
#define SM_TOTAL 178176
#define THRESH   0.025f
#define FINF     3.402823466e38f

__device__ float g_partial[256];

// ---------------- helpers ----------------
__device__ __forceinline__ uint32_t smem_u32(const void* p) {
    uint32_t a;
    asm("{ .reg .u64 t; cvta.to.shared.u64 t, %1; cvt.u32.u64 %0, t; }" : "=r"(a) : "l"(p));
    return a;
}
__device__ __forceinline__ void cp16(uint32_t dst, const void* src) {
    asm volatile("cp.async.cg.shared.global [%0], [%1], 16;" :: "r"(dst), "l"(src) : "memory");
}
__device__ __forceinline__ void cp_commit() { asm volatile("cp.async.commit_group;" ::: "memory"); }
__device__ __forceinline__ void cp_wait1()  { asm volatile("cp.async.wait_group 1;"  ::: "memory"); }

__device__ __forceinline__ void mma_f16(float& c0, float& c1, float& c2, float& c3,
                                        uint32_t a0, uint32_t a1, uint32_t a2, uint32_t a3,
                                        uint32_t b0, uint32_t b1) {
    asm volatile("mma.sync.aligned.m16n8k16.row.col.f32.f16.f16.f32 "
                 "{%0,%1,%2,%3}, {%4,%5,%6,%7}, {%8,%9}, {%0,%1,%2,%3};"
                 : "+f"(c0), "+f"(c1), "+f"(c2), "+f"(c3)
                 : "r"(a0), "r"(a1), "r"(a2), "r"(a3), "r"(b0), "r"(b1));
}

__device__ __forceinline__ void upd2(float v, int k, float& s1, int& i1, float& s2, int& i2) {
    if (v < s1)      { s2 = s1; i2 = i1; s1 = v; i1 = k; }
    else if (v < s2) { s2 = v; i2 = k; }
}

__device__ __forceinline__ void ins4(float v, int k,
                                     float& t1, int& j1, float& t2, int& j2,
                                     float& t3, int& j3, float& t4, int& j4) {
    if (v < t4) {
        if (v < t3) {
            if (v < t2) {
                if (v < t1) { t4=t3;j4=j3; t3=t2;j3=j2; t2=t1;j2=j1; t1=v;j1=k; }
                else        { t4=t3;j4=j3; t3=t2;j3=j2; t2=v;j2=k; }
            } else          { t4=t3;j4=j3; t3=v;j3=k; }
        } else              { t4=v;j4=k; }
    }
}

__device__ __forceinline__ void merge4(int off,
                                       float& t1, int& j1, float& t2, int& j2,
                                       float& t3, int& j3, float& t4, int& j4) {
    float o1 = __shfl_xor_sync(0xffffffffu, t1, off);
    float o2 = __shfl_xor_sync(0xffffffffu, t2, off);
    float o3 = __shfl_xor_sync(0xffffffffu, t3, off);
    float o4 = __shfl_xor_sync(0xffffffffu, t4, off);
    int   p1 = __shfl_xor_sync(0xffffffffu, j1, off);
    int   p2 = __shfl_xor_sync(0xffffffffu, j2, off);
    int   p3 = __shfl_xor_sync(0xffffffffu, j3, off);
    int   p4 = __shfl_xor_sync(0xffffffffu, j4, off);
    ins4(o1, p1, t1, j1, t2, j2, t3, j3, t4, j4);
    ins4(o2, p2, t1, j1, t2, j2, t3, j3, t4, j4);
    ins4(o3, p3, t1, j1, t2, j2, t3, j3, t4, j4);
    ins4(o4, p4, t1, j1, t2, j2, t3, j3, t4, j4);
}

__device__ __forceinline__ uint32_t h2bits(float a, float b) {
    __half2 h = __floats2half2_rn(a, b);
    return *reinterpret_cast<uint32_t*>(&h);
}

// ---------------- main persistent kernel ----------------
__global__ __launch_bounds__(256, 1) void vq_main_kernel(
    const float* __restrict__ inputs,
    const float* __restrict__ cwf,
    float* __restrict__ out,
    int grid)
{
    extern __shared__ char sm[];
    const uint32_t sb = smem_u32(sm);
    const int tid = threadIdx.x, wid = tid >> 5, lane = tid & 31;
    const int g = lane >> 2, q = lane & 3;

    // ---- stage first fp32 A tile (gets DRAM moving) ----
    {
        const float* src = inputs + (size_t)blockIdx.x * TILE_M * D;
        for (int i = tid; i < 2048; i += 256) cp16(sb + XS0_OFF + i * 16, src + i * 4);
        cp_commit();
    }

    // ---- codebook: fp32 gmem -> fp16 smem (padded rows) + 0.5*||c||^2 ----
    {
        float* hcs = reinterpret_cast<float*>(sm + HCSQ_OFF);
        for (int r = tid; r < KCW; r += 256) {
            const float4* src = reinterpret_cast<const float4*>(cwf + (size_t)r * D);
            char* dst = sm + CB_OFF + r * BSTRIDE;
            float ssum = 0.f;
            #pragma unroll
            for (int j = 0; j < 8; j++) {
                float4 v0 = src[2 * j], v1 = src[2 * j + 1];
                ssum += v0.x * v0.x + v0.y * v0.y + v0.z * v0.z + v0.w * v0.w
                      + v1.x * v1.x + v1.y * v1.y + v1.z * v1.z + v1.w * v1.w;
                uint4 w;
                w.x = h2bits(v0.x, v0.y); w.y = h2bits(v0.z, v0.w);
                w.z = h2bits(v1.x, v1.y); w.w = h2bits(v1.z, v1.w);
                *reinterpret_cast<uint4*>(dst + j * 16) = w;
            }
            hcs[r] = 0.5f * ssum;
        }
    }

    float lacc = 0.0f;
    int lt = 0;
    for (int t = blockIdx.x; t < NTILES; t += grid, lt++) {
        const int p = lt & 1;
        const int tn = t + grid;
        if (tn < NTILES) {
            const float* src = inputs + (size_t)tn * TILE_M * D;
            const uint32_t xs = sb + (p ? XS0_OFF : XS1_OFF);   // next buffer = 1-p
            for (int i = tid; i < 2048; i += 256) cp16(xs + i * 16, src + i * 4);
        }
        cp_commit();
        cp_wait1();          // current tile's staging complete
        __syncthreads();

        // ---- convert fp32 staging -> fp16 A tile (32 floats / thread) ----
        {
            const char* xs = sm + (p ? XS1_OFF : XS0_OFF);
            char*       ab = sm + (p ? A1_OFF  : A0_OFF);
            const int r = tid >> 1, h = tid & 1;
            const float4* s4 = reinterpret_cast<const float4*>(xs + r * 256 + h * 128);
            char* d = ab + r * BSTRIDE + h * 64;
            #pragma unroll
            for (int j = 0; j < 4; j++) {
                float4 v0 = s4[2 * j], v1 = s4[2 * j + 1];
                uint4 w;
                w.x = h2bits(v0.x, v0.y); w.y = h2bits(v0.z, v0.w);
                w.z = h2bits(v1.x, v1.y); w.w = h2bits(v1.z, v1.w);
                *reinterpret_cast<uint4*>(d + j * 16) = w;
            }
        }
        __syncthreads();

        // ---- A fragments (16 rows per warp) ----
        const char* abase = sm + (p ? A1_OFF : A0_OFF);
        uint32_t ah[4][4];
        {
            const char* pA = abase + (wid * 16 + g) * BSTRIDE + q * 4;
            const char* pB = pA + 8 * BSTRIDE;
            #pragma unroll
            for (int ks = 0; ks < 4; ks++) {
                ah[ks][0] = *(const uint32_t*)(pA + ks * 32);
                ah[ks][1] = *(const uint32_t*)(pB + ks * 32);
                ah[ks][2] = *(const uint32_t*)(pA + ks * 32 + 16);
                ah[ks][3] = *(const uint32_t*)(pB + ks * 32 + 16);
            }
        }

        float s1a = FINF, s2a = FINF, s1b = FINF, s2b = FINF;
        int   i1a = 0, i2a = 0, i1b = 0, i2b = 0;

        const char* bh_base = sm + CB_OFF + g * BSTRIDE + q * 4;
        const char* hc_base = sm + HCSQ_OFF + q * 8;

        for (int cn = 0; cn < 4; cn++) {            // 4 chunks of 128 codewords
            float acc[16][4];
            #pragma unroll
            for (int nt = 0; nt < 16; nt++) {
                acc[nt][0] = 0.f; acc[nt][1] = 0.f; acc[nt][2] = 0.f; acc[nt][3] = 0.f;
            }
            const char* bcn = bh_base + cn * 128 * BSTRIDE;
            #pragma unroll
            for (int ks = 0; ks < 4; ks++) {
                #pragma unroll
                for (int ng = 0; ng < 4; ng++) {
                    uint32_t b0[4], b1[4];
                    #pragma unroll
                    for (int u = 0; u < 4; u++) {
                        const char* pp = bcn + (ng * 4 + u) * 8 * BSTRIDE + ks * 32;
                        b0[u] = *(const uint32_t*)pp;
                        b1[u] = *(const uint32_t*)(pp + 16);
                    }
                    #pragma unroll
                    for (int u = 0; u < 4; u++) {
                        int nt = ng * 4 + u;
                        mma_f16(acc[nt][0], acc[nt][1], acc[nt][2], acc[nt][3],
                                ah[ks][0], ah[ks][1], ah[ks][2], ah[ks][3], b0[u], b1[u]);
                    }
                }
            }
            // chunk epilogue: score = 0.5||c||^2 - x.c ; per-lane top-2
            #pragma unroll
            for (int nt = 0; nt < 16; nt++) {
                float2 hc = *(const float2*)(hc_base + (cn * 128 + nt * 8) * 4);
                int col = cn * 128 + nt * 8 + 2 * q;
                upd2(hc.x - acc[nt][0], col,     s1a, i1a, s2a, i2a);
                upd2(hc.y - acc[nt][1], col + 1, s1a, i1a, s2a, i2a);
                upd2(hc.x - acc[nt][2], col,     s1b, i1b, s2b, i2b);
                upd2(hc.y - acc[nt][3], col + 1, s1b, i1b, s2b, i2b);
            }
        }

        // ---- merge per-lane top-2 across quad into global top-4 per row ----
        float ta1 = s1a, ta2 = s2a, ta3 = FINF, ta4 = FINF;
        int   ja1 = i1a, ja2 = i2a, ja3 = 0,    ja4 = 0;
        float tb1 = s1b, tb2 = s2b, tb3 = FINF, tb4 = FINF;
        int   jb1 = i1b, jb2 = i2b, jb3 = 0,    jb4 = 0;
        merge4(1, ta1, ja1, ta2, ja2, ta3, ja3, ta4, ja4);
        merge4(2, ta1, ja1, ta2, ja2, ta3, ja3, ta4, ja4);
        merge4(1, tb1, jb1, tb2, jb2, tb3, jb3, tb4, jb4);
        merge4(2, tb1, jb1, tb2, jb2, tb3, jb3, tb4, jb4);

        const int rowA = t * TILE_M + wid * 16 + g;

        // ---- exact fp32 refinement: always top-2, plus 3/4 if within THRESH ----
        int winA = 0, winB = 0;
        if (q < 2) {
            float cs0 = q ? tb1 : ta1, cs1 = q ? tb2 : ta2;
            float cs2 = q ? tb3 : ta3, cs3 = q ? tb4 : ta4;
            int   cj0 = q ? jb1 : ja1, cj1 = q ? jb2 : ja2;
            int   cj2 = q ? jb3 : ja3, cj3 = q ? jb4 : ja4;
            const int myrow = q ? rowA + 8 : rowA;
            const float4* x4 = reinterpret_cast<const float4*>(inputs + (size_t)myrow * D);

            float bestd = FINF; int bidx = 0;
            float css[4] = {cs0, cs1, cs2, cs3};
            int   cjj[4] = {cj0, cj1, cj2, cj3};
            #pragma unroll
            for (int c = 0; c < 4; c++) {
                if (c < 2 || css[c] - css[0] < THRESH) {
                    const float4* c4 = reinterpret_cast<const float4*>(cwf + (size_t)cjj[c] * D);
                    float dd = 0.f;
                    #pragma unroll
                    for (int j = 0; j < 16; j++) {
                        float4 xv = x4[j], cv = c4[j];
                        float e;
                        e = xv.x - cv.x; dd = fmaf(e, e, dd);
                        e = xv.y - cv.y; dd = fmaf(e, e, dd);
                        e = xv.z - cv.z; dd = fmaf(e, e, dd);
                        e = xv.w - cv.w; dd = fmaf(e, e, dd);
                    }
                    if (dd < bestd || (dd == bestd && cjj[c] < bidx)) { bestd = dd; bidx = cjj[c]; }
                }
            }
            out[(size_t)NROWS * D + myrow] = (float)bidx;
            lacc += bestd;
            if (q == 0) winA = bidx; else winB = bidx;
        }

        // ---- gather winners' exact fp32 codewords cooperatively (quad) ----
        const int bl = lane & ~3;
        const int bA = __shfl_sync(0xffffffffu, winA, bl);
        const int bB = __shfl_sync(0xffffffffu, winB, bl + 1);
        {
            const float4* cA = reinterpret_cast<const float4*>(cwf + (size_t)bA * D);
            const float4* cB = reinterpret_cast<const float4*>(cwf + (size_t)bB * D);
            float4* oA = reinterpret_cast<float4*>(out + (size_t)rowA * D);
            float4* oB = reinterpret_cast<float4*>(out + (size_t)(rowA + 8) * D);
            #pragma unroll
            for (int j = 0; j < 4; j++) {
                oA[q * 4 + j] = cA[q * 4 + j];
                oB[q * 4 + j] = cB[q * 4 + j];
            }
        }
    }

    // ---- block loss reduction -> per-block partial (no init kernel needed) ----
    #pragma unroll
    for (int off = 16; off; off >>= 1) lacc += __shfl_xor_sync(0xffffffffu, lacc, off);
    __shared__ float wred[8];
    if (lane == 0) wred[wid] = lacc;
    __syncthreads();
    if (tid == 0) {
        float s = 0.f;
        #pragma unroll
        for (int w = 0; w < 8; w++) s += wred[w];
        g_partial[blockIdx.x] = s;
    }
}

__global__ void vq_finish_kernel(float* __restrict__ out, int n) {
    float s = 0.f;
    for (int i = threadIdx.x; i < n; i += 32) s += g_partial[i];
    #pragma unroll
    for (int off = 16; off; off >>= 1) s += __shfl_xor_sync(0xffffffffu, s, off);
    if (threadIdx.x == 0)
        out[(size_t)NROWS * D + NROWS] = 0.25f * s / (float)((size_t)NROWS * D);
}

// ---------------- launch ----------------
extern "C" void kernel_launch(void* const* d_in, const int* in_sizes, int n_in,
                              void* d_out, int out_size) {
    const float* inputs    = (const float*)d_in[0];
    const float* codewords = (const float*)d_in[1];
    float* out = (float*)d_out;

    int sms = 148;
    cudaDeviceGetAttribute(&sms, cudaDevAttrMultiProcessorCount, 0);
    if (sms > NTILES) sms = NTILES;
    if (sms > 256)    sms = 256;

    cudaFuncSetAttribute(vq_main_kernel,
                         cudaFuncAttributeMaxDynamicSharedMemorySize, SM_TOTAL);

    vq_main_kernel<<<sms, 256, SM_TOTAL>>>(inputs, codewords, out, sms);
    vq_finish_kernel<<<1, 32>>>(out, sms);
}

// round 5
// speedup vs baseline: 4.8124x; 1.9273x over previous
#include <cuda_runtime.h>
#include <cuda_fp16.h>
#include <cstdint>

#define D       64
#define KCW     512
#define NROWS   262144
#define TILE_M  128
#define NTILES  (NROWS / TILE_M)

#define BSTRIDE  144            // 64 fp16 = 128B + 16B pad -> conflict-free LDS
#define CB_OFF   0              // 512*144 = 73728
#define HCSQ_OFF 73728          // 512 f32
#define XS0_OFF  75776          // fp32 staging 128*256B
#define XS1_OFF  108544
#define A0_OFF   141312         // fp16 tile 128*144
#define A1_OFF   159744
#define XSQ0_OFF 178176        // 128 f32
#define XSQ1_OFF 178688
#define MB0_OFF  179200
#define MB1_OFF  179208
#define SM_TOTAL 179456
#define THRESH   0.06f
#define FINF     3.402823466e38f

__device__ float g_partial[256];
__device__ int   g_counter;

// ---------------- helpers ----------------
__device__ __forceinline__ uint32_t smem_u32(const void* p) {
    uint32_t a;
    asm("{ .reg .u64 t; cvta.to.shared.u64 t, %1; cvt.u32.u64 %0, t; }" : "=r"(a) : "l"(p));
    return a;
}
__device__ __forceinline__ void mbar_init(uint32_t a, uint32_t cnt) {
    asm volatile("mbarrier.init.shared.b64 [%0], %1;" :: "r"(a), "r"(cnt) : "memory");
}
__device__ __forceinline__ void mbar_expect_tx(uint32_t a, uint32_t bytes) {
    asm volatile("mbarrier.arrive.expect_tx.shared.b64 _, [%0], %1;" :: "r"(a), "r"(bytes) : "memory");
}
__device__ __forceinline__ void bulk_g2s(uint32_t dst, const void* src, uint32_t bytes, uint32_t mbar) {
    asm volatile("cp.async.bulk.shared::cluster.global.mbarrier::complete_tx::bytes [%0], [%1], %2, [%3];"
                 :: "r"(dst), "l"(src), "r"(bytes), "r"(mbar) : "memory");
}
__device__ __forceinline__ void bar_wait(uint32_t a, uint32_t parity) {
    asm volatile(
        "{\n\t.reg .pred P;\n"
        "W%=:\n\t"
        "mbarrier.try_wait.parity.acquire.cta.shared::cta.b64 P, [%0], %1, 0x989680;\n\t"
        "@P bra DONE%=;\n\t"
        "bra W%=;\n"
        "DONE%=:\n\t}"
        :: "r"(a), "r"(parity) : "memory");
}
__device__ __forceinline__ void mma_f16(float& c0, float& c1, float& c2, float& c3,
                                        uint32_t a0, uint32_t a1, uint32_t a2, uint32_t a3,
                                        uint32_t b0, uint32_t b1) {
    asm volatile("mma.sync.aligned.m16n8k16.row.col.f32.f16.f16.f32 "
                 "{%0,%1,%2,%3}, {%4,%5,%6,%7}, {%8,%9}, {%0,%1,%2,%3};"
                 : "+f"(c0), "+f"(c1), "+f"(c2), "+f"(c3)
                 : "r"(a0), "r"(a1), "r"(a2), "r"(a3), "r"(b0), "r"(b1));
}
__device__ __forceinline__ uint32_t h2bits(float a, float b) {
    __half2 h = __floats2half2_rn(a, b);
    return *reinterpret_cast<uint32_t*>(&h);
}
// float -> order-preserving uint, low 9 bits replaced by index
__device__ __forceinline__ uint32_t packsc(float v, int k) {
    uint32_t u = __float_as_uint(v);
    u ^= (uint32_t)(((int32_t)u >> 31)) | 0x80000000u;
    return (u & 0xFFFFFE00u) | (uint32_t)k;
}
__device__ __forceinline__ float unpacksc(uint32_t p) {
    uint32_t u = p & 0xFFFFFE00u;
    uint32_t mask = 0x80000000u | ~(uint32_t)((int32_t)u >> 31);
    return __uint_as_float(u ^ mask);
}
__device__ __forceinline__ void updp(uint32_t v, uint32_t& s1, uint32_t& s2) {
    uint32_t hi = (s1 > v) ? s1 : v;
    s1 = (s1 < v) ? s1 : v;
    s2 = (s2 < hi) ? s2 : hi;
}
__device__ __forceinline__ void ins4u(uint32_t v, uint32_t& t1, uint32_t& t2, uint32_t& t3, uint32_t& t4) {
    if (v < t4) {
        if (v < t3) {
            if (v < t2) {
                if (v < t1) { t4 = t3; t3 = t2; t2 = t1; t1 = v; }
                else        { t4 = t3; t3 = t2; t2 = v; }
            } else          { t4 = t3; t3 = v; }
        } else              { t4 = v; }
    }
}
__device__ __forceinline__ void merge4u(int off, uint32_t& t1, uint32_t& t2, uint32_t& t3, uint32_t& t4) {
    uint32_t o1 = __shfl_xor_sync(0xffffffffu, t1, off);
    uint32_t o2 = __shfl_xor_sync(0xffffffffu, t2, off);
    uint32_t o3 = __shfl_xor_sync(0xffffffffu, t3, off);
    uint32_t o4 = __shfl_xor_sync(0xffffffffu, t4, off);
    ins4u(o1, t1, t2, t3, t4);
    ins4u(o2, t1, t2, t3, t4);
    ins4u(o3, t1, t2, t3, t4);
    ins4u(o4, t1, t2, t3, t4);
}

// ---------------- single persistent kernel ----------------
__global__ __launch_bounds__(256, 1) void vq_main_kernel(
    const float* __restrict__ inputs,
    const float* __restrict__ cwf,
    float* __restrict__ out,
    int grid)
{
    extern __shared__ char sm[];
    const uint32_t sb = smem_u32(sm);
    const int tid = threadIdx.x, wid = tid >> 5, lane = tid & 31;
    const int g = lane >> 2, q = lane & 3;

    const uint32_t MB[2]  = {sb + MB0_OFF, sb + MB1_OFF};
    const uint32_t XS[2]  = {sb + XS0_OFF, sb + XS1_OFF};

    if (tid == 0) { mbar_init(MB[0], 1); mbar_init(MB[1], 1); }
    __syncthreads();

    // kick off first tile's bulk load
    if (tid == 0) {
        mbar_expect_tx(MB[0], TILE_M * D * 4);
        bulk_g2s(XS[0], inputs + (size_t)blockIdx.x * TILE_M * D, TILE_M * D * 4, MB[0]);
    }

    // ---- codebook: fp32 gmem -> fp16 smem (padded rows) + 0.5*||c||^2 ----
    {
        float* hcs = reinterpret_cast<float*>(sm + HCSQ_OFF);
        for (int r = tid; r < KCW; r += 256) {
            const float4* src = reinterpret_cast<const float4*>(cwf + (size_t)r * D);
            char* dst = sm + CB_OFF + r * BSTRIDE;
            float ssum = 0.f;
            #pragma unroll
            for (int j = 0; j < 8; j++) {
                float4 v0 = src[2 * j], v1 = src[2 * j + 1];
                ssum += v0.x * v0.x + v0.y * v0.y + v0.z * v0.z + v0.w * v0.w
                      + v1.x * v1.x + v1.y * v1.y + v1.z * v1.z + v1.w * v1.w;
                uint4 w;
                w.x = h2bits(v0.x, v0.y); w.y = h2bits(v0.z, v0.w);
                w.z = h2bits(v1.x, v1.y); w.w = h2bits(v1.z, v1.w);
                *reinterpret_cast<uint4*>(dst + j * 16) = w;
            }
            hcs[r] = 0.5f * ssum;
        }
    }

    uint32_t ph[2] = {0u, 0u};
    float lacc = 0.0f;
    int lt = 0;
    for (int t = blockIdx.x; t < NTILES; t += grid, lt++) {
        const int p = lt & 1, np = p ^ 1;
        const int tn = t + grid;
        if (tn < NTILES && tid == 0) {
            mbar_expect_tx(MB[np], TILE_M * D * 4);
            bulk_g2s(XS[np], inputs + (size_t)tn * TILE_M * D, TILE_M * D * 4, MB[np]);
        }

        bar_wait(MB[p], ph[p]);
        ph[p] ^= 1;

        // ---- convert fp32 staging -> fp16 tile + per-row ||x||^2 ----
        {
            const char* xs = sm + (p ? XS1_OFF : XS0_OFF);
            char*       ab = sm + (p ? A1_OFF  : A0_OFF);
            float*      xq = reinterpret_cast<float*>(sm + (p ? XSQ1_OFF : XSQ0_OFF));
            const int r = tid >> 1, h = tid & 1;
            const float4* s4 = reinterpret_cast<const float4*>(xs + r * 256 + h * 128);
            char* d = ab + r * BSTRIDE + h * 64;
            float part = 0.f;
            #pragma unroll
            for (int j = 0; j < 4; j++) {
                float4 v0 = s4[2 * j], v1 = s4[2 * j + 1];
                part += v0.x * v0.x + v0.y * v0.y + v0.z * v0.z + v0.w * v0.w
                      + v1.x * v1.x + v1.y * v1.y + v1.z * v1.z + v1.w * v1.w;
                uint4 w;
                w.x = h2bits(v0.x, v0.y); w.y = h2bits(v0.z, v0.w);
                w.z = h2bits(v1.x, v1.y); w.w = h2bits(v1.z, v1.w);
                *reinterpret_cast<uint4*>(d + j * 16) = w;
            }
            part += __shfl_xor_sync(0xffffffffu, part, 1);
            if (h == 0) xq[r] = part;
        }
        __syncthreads();

        // ---- A fragments (16 rows per warp) ----
        const char* abase = sm + (p ? A1_OFF : A0_OFF);
        uint32_t ah[4][4];
        {
            const char* pA = abase + (wid * 16 + g) * BSTRIDE + q * 4;
            const char* pB = pA + 8 * BSTRIDE;
            #pragma unroll
            for (int ks = 0; ks < 4; ks++) {
                ah[ks][0] = *(const uint32_t*)(pA + ks * 32);
                ah[ks][1] = *(const uint32_t*)(pB + ks * 32);
                ah[ks][2] = *(const uint32_t*)(pA + ks * 32 + 16);
                ah[ks][3] = *(const uint32_t*)(pB + ks * 32 + 16);
            }
        }

        uint32_t s1a = 0xFFFFFFFFu, s2a = 0xFFFFFFFFu;
        uint32_t s1b = 0xFFFFFFFFu, s2b = 0xFFFFFFFFu;

        const char* bh_base = sm + CB_OFF + g * BSTRIDE + q * 4;
        const char* hc_base = sm + HCSQ_OFF + q * 8;

        for (int cn = 0; cn < 4; cn++) {            // 4 chunks of 128 codewords
            float acc[16][4];
            #pragma unroll
            for (int nt = 0; nt < 16; nt++) {
                acc[nt][0] = 0.f; acc[nt][1] = 0.f; acc[nt][2] = 0.f; acc[nt][3] = 0.f;
            }
            const char* bcn = bh_base + cn * 128 * BSTRIDE;
            #pragma unroll
            for (int ks = 0; ks < 4; ks++) {
                #pragma unroll
                for (int ng = 0; ng < 4; ng++) {
                    uint32_t b0[4], b1[4];
                    #pragma unroll
                    for (int u = 0; u < 4; u++) {
                        const char* pp = bcn + (ng * 4 + u) * 8 * BSTRIDE + ks * 32;
                        b0[u] = *(const uint32_t*)pp;
                        b1[u] = *(const uint32_t*)(pp + 16);
                    }
                    #pragma unroll
                    for (int u = 0; u < 4; u++) {
                        int nt = ng * 4 + u;
                        mma_f16(acc[nt][0], acc[nt][1], acc[nt][2], acc[nt][3],
                                ah[ks][0], ah[ks][1], ah[ks][2], ah[ks][3], b0[u], b1[u]);
                    }
                }
            }
            // chunk epilogue: score = 0.5||c||^2 - x.c ; packed-uint top-2
            #pragma unroll
            for (int nt = 0; nt < 16; nt++) {
                float2 hc = *(const float2*)(hc_base + (cn * 128 + nt * 8) * 4);
                int col = cn * 128 + nt * 8 + 2 * q;
                updp(packsc(hc.x - acc[nt][0], col),     s1a, s2a);
                updp(packsc(hc.y - acc[nt][1], col + 1), s1a, s2a);
                updp(packsc(hc.x - acc[nt][2], col),     s1b, s2b);
                updp(packsc(hc.y - acc[nt][3], col + 1), s1b, s2b);
            }
        }

        // ---- quad merge into top-4 per row ----
        uint32_t ta1 = s1a, ta2 = s2a, ta3 = 0xFFFFFFFFu, ta4 = 0xFFFFFFFFu;
        uint32_t tb1 = s1b, tb2 = s2b, tb3 = 0xFFFFFFFFu, tb4 = 0xFFFFFFFFu;
        merge4u(1, ta1, ta2, ta3, ta4);
        merge4u(2, ta1, ta2, ta3, ta4);
        merge4u(1, tb1, tb2, tb3, tb4);
        merge4u(2, tb1, tb2, tb3, tb4);

        const int rowA = t * TILE_M + wid * 16 + g;

        // ---- finalize: conditional exact refinement ----
        int winA = 0, winB = 0;
        if (q < 2) {
            uint32_t c1 = q ? tb1 : ta1, c2 = q ? tb2 : ta2;
            uint32_t c3 = q ? tb3 : ta3, c4 = q ? tb4 : ta4;
            const int myrow = q ? rowA + 8 : rowA;
            const int rlocal = q ? wid * 16 + g + 8 : wid * 16 + g;
            const float xsq = reinterpret_cast<const float*>(sm + (p ? XSQ1_OFF : XSQ0_OFF))[rlocal];
            float f1 = unpacksc(c1), f2 = unpacksc(c2);
            int bidx;
            float dist;
            if (f2 - f1 >= THRESH) {
                bidx = (int)(c1 & 511u);
                dist = fmaf(2.0f, f1, xsq);
            } else {
                float f3 = unpacksc(c3), f4 = unpacksc(c4);
                float css[4] = {f1, f2, f3, f4};
                int   cjj[4] = {(int)(c1 & 511u), (int)(c2 & 511u), (int)(c3 & 511u), (int)(c4 & 511u)};
                const float4* x4 = reinterpret_cast<const float4*>(inputs + (size_t)myrow * D);
                float bestd = FINF; bidx = 0;
                #pragma unroll
                for (int c = 0; c < 4; c++) {
                    if (c < 2 || css[c] - f1 < THRESH) {
                        const float4* c4p = reinterpret_cast<const float4*>(cwf + (size_t)cjj[c] * D);
                        float dd = 0.f;
                        #pragma unroll
                        for (int j = 0; j < 16; j++) {
                            float4 xv = x4[j], cv = c4p[j];
                            float e;
                            e = xv.x - cv.x; dd = fmaf(e, e, dd);
                            e = xv.y - cv.y; dd = fmaf(e, e, dd);
                            e = xv.z - cv.z; dd = fmaf(e, e, dd);
                            e = xv.w - cv.w; dd = fmaf(e, e, dd);
                        }
                        if (dd < bestd || (dd == bestd && cjj[c] < bidx)) { bestd = dd; bidx = cjj[c]; }
                    }
                }
                dist = bestd;
            }
            out[(size_t)NROWS * D + myrow] = (float)bidx;
            lacc += dist;
            if (q == 0) winA = bidx; else winB = bidx;
        }

        // ---- gather winners' exact fp32 codewords cooperatively (quad) ----
        const int bl = lane & ~3;
        const int bA = __shfl_sync(0xffffffffu, winA, bl);
        const int bB = __shfl_sync(0xffffffffu, winB, bl + 1);
        {
            const float4* cA = reinterpret_cast<const float4*>(cwf + (size_t)bA * D);
            const float4* cB = reinterpret_cast<const float4*>(cwf + (size_t)bB * D);
            float4* oA = reinterpret_cast<float4*>(out + (size_t)rowA * D);
            float4* oB = reinterpret_cast<float4*>(out + (size_t)(rowA + 8) * D);
            #pragma unroll
            for (int j = 0; j < 4; j++) {
                oA[q * 4 + j] = cA[q * 4 + j];
                oB[q * 4 + j] = cB[q * 4 + j];
            }
        }
    }

    // ---- loss: block reduce -> partial; last block finalizes ----
    #pragma unroll
    for (int off = 16; off; off >>= 1) lacc += __shfl_xor_sync(0xffffffffu, lacc, off);
    __shared__ float wred[8];
    if (lane == 0) wred[wid] = lacc;
    __syncthreads();
    if (tid == 0) {
        float s = 0.f;
        #pragma unroll
        for (int w = 0; w < 8; w++) s += wred[w];
        g_partial[blockIdx.x] = s;
        __threadfence();
        int ticket = atomicAdd(&g_counter, 1);
        if (ticket == grid - 1) {
            float tot = 0.f;
            for (int i = 0; i < grid; i++) tot += g_partial[i];
            out[(size_t)NROWS * D + NROWS] = 0.25f * tot / (float)((size_t)NROWS * D);
            g_counter = 0;   // reset for next graph replay
        }
    }
}

// ---------------- launch ----------------
extern "C" void kernel_launch(void* const* d_in, const int* in_sizes, int n_in,
                              void* d_out, int out_size) {
    const float* inputs    = (const float*)d_in[0];
    const float* codewords = (const float*)d_in[1];
    float* out = (float*)d_out;

    int sms = 148;
    cudaDeviceGetAttribute(&sms, cudaDevAttrMultiProcessorCount, 0);
    if (sms > NTILES) sms = NTILES;
    if (sms > 256)    sms = 256;

    cudaFuncSetAttribute(vq_main_kernel,
                         cudaFuncAttributeMaxDynamicSharedMemorySize, SM_TOTAL);

    vq_main_kernel<<<sms, 256, SM_TOTAL>>>(inputs, codewords, out, sms);
}

// round 6
// speedup vs baseline: 6.4220x; 1.3345x over previous
#include <cuda_runtime.h>
#include <cuda_fp16.h>
#include <cstdint>

#define D       64
#define KCW     512
#define NROWS   262144
#define TILE_M  256
#define NTILES  (NROWS / TILE_M)   // 1024

#define BSTRIDE  144               // 64 fp16 = 128B + 16B pad
#define CB_OFF   0                 // 512*144 = 73728
#define HCSQ_OFF 73728             // 2048 -> 75776
#define XSTG_OFF 75776             // fp32 staging 256*256 = 65536 -> 141312
#define A0_OFF   141312            // fp16 tile 256*144 = 36864 -> 178176
#define A1_OFF   178176            // -> 215040
#define XSQ0_OFF 215040            // 1024 -> 216064
#define XSQ1_OFF 216064            // 1024 -> 217088
#define MB_OFF   217088
#define SM_TOTAL 217344
#define THRESH   0.08f
#define FINF     3.402823466e38f
#define PINF     __int_as_float(0x7f800000)

__device__ float g_partial[256];
__device__ int   g_counter;

// ---------------- helpers ----------------
__device__ __forceinline__ uint32_t smem_u32(const void* p) {
    uint32_t a;
    asm("{ .reg .u64 t; cvta.to.shared.u64 t, %1; cvt.u32.u64 %0, t; }" : "=r"(a) : "l"(p));
    return a;
}
__device__ __forceinline__ void mbar_init(uint32_t a, uint32_t cnt) {
    asm volatile("mbarrier.init.shared.b64 [%0], %1;" :: "r"(a), "r"(cnt) : "memory");
}
__device__ __forceinline__ void mbar_expect_tx(uint32_t a, uint32_t bytes) {
    asm volatile("mbarrier.arrive.expect_tx.shared.b64 _, [%0], %1;" :: "r"(a), "r"(bytes) : "memory");
}
__device__ __forceinline__ void bulk_g2s(uint32_t dst, const void* src, uint32_t bytes, uint32_t mbar) {
    asm volatile("cp.async.bulk.shared::cluster.global.mbarrier::complete_tx::bytes [%0], [%1], %2, [%3];"
                 :: "r"(dst), "l"(src), "r"(bytes), "r"(mbar) : "memory");
}
__device__ __forceinline__ void bar_wait(uint32_t a, uint32_t parity) {
    asm volatile(
        "{\n\t.reg .pred P;\n"
        "W%=:\n\t"
        "mbarrier.try_wait.parity.acquire.cta.shared::cta.b64 P, [%0], %1, 0x989680;\n\t"
        "@P bra DONE%=;\n\t"
        "bra W%=;\n"
        "DONE%=:\n\t}"
        :: "r"(a), "r"(parity) : "memory");
}
__device__ __forceinline__ void mma_f16(float& c0, float& c1, float& c2, float& c3,
                                        uint32_t a0, uint32_t a1, uint32_t a2, uint32_t a3,
                                        uint32_t b0, uint32_t b1) {
    asm volatile("mma.sync.aligned.m16n8k16.row.col.f32.f16.f16.f32 "
                 "{%0,%1,%2,%3}, {%4,%5,%6,%7}, {%8,%9}, {%0,%1,%2,%3};"
                 : "+f"(c0), "+f"(c1), "+f"(c2), "+f"(c3)
                 : "r"(a0), "r"(a1), "r"(a2), "r"(a3), "r"(b0), "r"(b1));
}
__device__ __forceinline__ void ldsm_x4(uint32_t* r, uint32_t addr) {
    asm volatile("ldmatrix.sync.aligned.m8n8.x4.shared.b16 {%0,%1,%2,%3}, [%4];"
                 : "=r"(r[0]), "=r"(r[1]), "=r"(r[2]), "=r"(r[3]) : "r"(addr));
}
__device__ __forceinline__ uint32_t h2bits(float a, float b) {
    __half2 h = __floats2half2_rn(a, b);
    return *reinterpret_cast<uint32_t*>(&h);
}
// score + index -> float with low 9 mantissa bits replaced by index; insert into top-2
__device__ __forceinline__ void ins2(float v, uint32_t col, float& s1, float& s2) {
    float pf = __uint_as_float((__float_as_uint(v) & 0xFFFFFE00u) | col);
    float mx = fmaxf(s1, pf);
    s1 = fminf(s1, pf);
    s2 = fminf(s2, mx);
}
__device__ __forceinline__ void ins4f(float v, float& t1, float& t2, float& t3, float& t4) {
    if (v < t4) {
        if (v < t3) {
            if (v < t2) {
                if (v < t1) { t4 = t3; t3 = t2; t2 = t1; t1 = v; }
                else        { t4 = t3; t3 = t2; t2 = v; }
            } else          { t4 = t3; t3 = v; }
        } else              { t4 = v; }
    }
}

// ---------------- single persistent kernel ----------------
__global__ __launch_bounds__(256, 1) void vq_main_kernel(
    const float* __restrict__ inputs,
    const float* __restrict__ cwf,
    float* __restrict__ out,
    int grid)
{
    extern __shared__ char sm[];
    const uint32_t sb = smem_u32(sm);
    const int tid = threadIdx.x, wid = tid >> 5, lane = tid & 31;
    const int g = lane >> 2, q = lane & 3;

    if (tid == 0) mbar_init(sb + MB_OFF, 1);
    __syncthreads();
    if (tid == 0) {
        mbar_expect_tx(sb + MB_OFF, TILE_M * D * 4);
        bulk_g2s(sb + XSTG_OFF, inputs + (size_t)blockIdx.x * TILE_M * D, TILE_M * D * 4, sb + MB_OFF);
    }

    // ---- codebook: fp32 gmem -> fp16 smem rows + 0.5*||c||^2 ----
    {
        float* hcs = reinterpret_cast<float*>(sm + HCSQ_OFF);
        for (int r = tid; r < KCW; r += 256) {
            const float4* src = reinterpret_cast<const float4*>(cwf + (size_t)r * D);
            char* dst = sm + CB_OFF + r * BSTRIDE;
            float ssum = 0.f;
            #pragma unroll
            for (int j = 0; j < 8; j++) {
                float4 v0 = src[2 * j], v1 = src[2 * j + 1];
                ssum += v0.x * v0.x + v0.y * v0.y + v0.z * v0.z + v0.w * v0.w
                      + v1.x * v1.x + v1.y * v1.y + v1.z * v1.z + v1.w * v1.w;
                uint4 w;
                w.x = h2bits(v0.x, v0.y); w.y = h2bits(v0.z, v0.w);
                w.z = h2bits(v1.x, v1.y); w.w = h2bits(v1.z, v1.w);
                *reinterpret_cast<uint4*>(dst + j * 16) = w;
            }
            hcs[r] = 0.5f * ssum;
        }
    }

    // per-thread ldmatrix base addresses
    // B matrices order per x4: (nt0,kh0),(nt0,kh1),(nt1,kh0),(nt1,kh1)
    const uint32_t Bbase = sb + CB_OFF + (uint32_t)(((lane >> 4) * 8 + (lane & 7)) * BSTRIDE + ((lane >> 3) & 1) * 16);
    // A matrices order per x4: (r0-7,kh0),(r8-15,kh0),(r0-7,kh1),(r8-15,kh1)
    const uint32_t Arowoff = (uint32_t)((((lane >> 3) & 1) * 8 + (lane & 7)) * BSTRIDE + (lane >> 4) * 16);

    uint32_t phase = 0;
    float lacc = 0.0f;
    int lt = 0;
    for (int t = blockIdx.x; t < NTILES; t += grid, lt++) {
        const int p = lt & 1;
        bar_wait(sb + MB_OFF, phase); phase ^= 1;
        const uint32_t Aoff = p ? A1_OFF : A0_OFF;

        // ---- convert fp32 staging -> fp16 tile + per-row ||x||^2 (1 row/thread) ----
        {
            const char* srow = sm + XSTG_OFF + tid * 256;
            char* drow = sm + Aoff + tid * BSTRIDE;
            float* xqb = reinterpret_cast<float*>(sm + (p ? XSQ1_OFF : XSQ0_OFF));
            float ssum = 0.f;
            #pragma unroll
            for (int jj = 0; jj < 16; jj++) {
                int c = (jj + tid) & 15;
                float4 v = *reinterpret_cast<const float4*>(srow + c * 16);
                ssum += v.x * v.x + v.y * v.y + v.z * v.z + v.w * v.w;
                uint2 w;
                w.x = h2bits(v.x, v.y); w.y = h2bits(v.z, v.w);
                *reinterpret_cast<uint2*>(drow + c * 8) = w;
            }
            xqb[tid] = ssum;
        }
        __syncthreads();   // tile converted; staging free; codebook visible (iter 0)

        const int tn = t + grid;
        if (tn < NTILES && tid == 0) {
            mbar_expect_tx(sb + MB_OFF, TILE_M * D * 4);
            bulk_g2s(sb + XSTG_OFF, inputs + (size_t)tn * TILE_M * D, TILE_M * D * 4, sb + MB_OFF);
        }

        // ---- A fragments: 32 rows/warp, 2 groups x 4 ks via ldmatrix ----
        uint32_t ah[2][4][4];
        {
            const uint32_t abase = sb + Aoff + (uint32_t)(wid * 32) * BSTRIDE + Arowoff;
            #pragma unroll
            for (int grp = 0; grp < 2; grp++)
                #pragma unroll
                for (int ks = 0; ks < 4; ks++)
                    ldsm_x4(ah[grp][ks], abase + grp * 16 * BSTRIDE + ks * 32);
        }

        float s1[4] = {PINF, PINF, PINF, PINF};
        float s2[4] = {PINF, PINF, PINF, PINF};

        for (int cn = 0; cn < 8; cn++) {            // 8 chunks of 64 codewords
            float acc[64];
            #pragma unroll
            for (int i = 0; i < 64; i++) acc[i] = 0.f;

            const uint32_t bc = Bbase + (uint32_t)cn * (64 * BSTRIDE);
            #pragma unroll
            for (int ks = 0; ks < 4; ks++) {
                #pragma unroll
                for (int pr = 0; pr < 4; pr++) {
                    uint32_t b[4];
                    ldsm_x4(b, bc + pr * (16 * BSTRIDE) + ks * 32);
                    const int n0 = pr * 16, n1 = n0 + 8;
                    mma_f16(acc[n0+0], acc[n0+1], acc[n0+2], acc[n0+3],
                            ah[0][ks][0], ah[0][ks][1], ah[0][ks][2], ah[0][ks][3], b[0], b[1]);
                    mma_f16(acc[n0+4], acc[n0+5], acc[n0+6], acc[n0+7],
                            ah[1][ks][0], ah[1][ks][1], ah[1][ks][2], ah[1][ks][3], b[0], b[1]);
                    mma_f16(acc[n1+0], acc[n1+1], acc[n1+2], acc[n1+3],
                            ah[0][ks][0], ah[0][ks][1], ah[0][ks][2], ah[0][ks][3], b[2], b[3]);
                    mma_f16(acc[n1+4], acc[n1+5], acc[n1+6], acc[n1+7],
                            ah[1][ks][0], ah[1][ks][1], ah[1][ks][2], ah[1][ks][3], b[2], b[3]);
                }
            }
            // chunk epilogue: score = 0.5||c||^2 - x.c ; packed-float top-2 per row-group
            #pragma unroll
            for (int nt = 0; nt < 8; nt++) {
                float2 hc = *reinterpret_cast<const float2*>(sm + HCSQ_OFF + q * 8 + cn * 256 + nt * 32);
                uint32_t colA = (uint32_t)(cn * 64 + nt * 8 + 2 * q);
                uint32_t colB = colA + 1;
                const int nb = nt * 8;
                ins2(hc.x - acc[nb + 0], colA, s1[0], s2[0]);
                ins2(hc.y - acc[nb + 1], colB, s1[0], s2[0]);
                ins2(hc.x - acc[nb + 2], colA, s1[1], s2[1]);
                ins2(hc.y - acc[nb + 3], colB, s1[1], s2[1]);
                ins2(hc.x - acc[nb + 4], colA, s1[2], s2[2]);
                ins2(hc.y - acc[nb + 5], colB, s1[2], s2[2]);
                ins2(hc.x - acc[nb + 6], colA, s1[3], s2[3]);
                ins2(hc.y - acc[nb + 7], colB, s1[3], s2[3]);
            }
        }

        // ---- quad merge each row-group into top-4; lane q keeps row-group q ----
        float m1 = PINF, m2 = PINF, m3 = PINF, m4 = PINF;
        #pragma unroll
        for (int rg = 0; rg < 4; rg++) {
            float t1 = s1[rg], t2 = s2[rg], t3 = PINF, t4 = PINF;
            #pragma unroll
            for (int off = 1; off <= 2; off <<= 1) {
                float o1 = __shfl_xor_sync(0xffffffffu, t1, off);
                float o2 = __shfl_xor_sync(0xffffffffu, t2, off);
                float o3 = __shfl_xor_sync(0xffffffffu, t3, off);
                float o4 = __shfl_xor_sync(0xffffffffu, t4, off);
                ins4f(o1, t1, t2, t3, t4);
                ins4f(o2, t1, t2, t3, t4);
                ins4f(o3, t1, t2, t3, t4);
                ins4f(o4, t1, t2, t3, t4);
            }
            if (q == rg) { m1 = t1; m2 = t2; m3 = t3; m4 = t4; }
        }

        const int rowbase = t * TILE_M + wid * 32;
        const int myrow = rowbase + q * 8 + g;
        const float xsq = reinterpret_cast<const float*>(sm + (p ? XSQ1_OFF : XSQ0_OFF))[wid * 32 + q * 8 + g];

        const uint32_t u1 = __float_as_uint(m1);
        const float f1 = __uint_as_float(u1 & 0xFFFFFE00u);
        const float f2 = __uint_as_float(__float_as_uint(m2) & 0xFFFFFE00u);
        int bidx; float dist;
        if (f2 - f1 >= THRESH) {
            bidx = (int)(u1 & 511u);
            dist = fmaf(2.0f, f1, xsq);
        } else {
            const uint32_t u2 = __float_as_uint(m2), u3 = __float_as_uint(m3), u4 = __float_as_uint(m4);
            float css[4] = {f1, f2,
                            __uint_as_float(u3 & 0xFFFFFE00u),
                            __uint_as_float(u4 & 0xFFFFFE00u)};
            int cjj[4] = {(int)(u1 & 511u), (int)(u2 & 511u), (int)(u3 & 511u), (int)(u4 & 511u)};
            const float4* x4 = reinterpret_cast<const float4*>(inputs + (size_t)myrow * D);
            float bestd = FINF; bidx = 0;
            #pragma unroll
            for (int c = 0; c < 4; c++) {
                if (c < 2 || css[c] - f1 < THRESH) {
                    const float4* c4p = reinterpret_cast<const float4*>(cwf + (size_t)cjj[c] * D);
                    float dd = 0.f;
                    #pragma unroll
                    for (int j = 0; j < 16; j++) {
                        float4 xv = x4[j], cv = c4p[j];
                        float e;
                        e = xv.x - cv.x; dd = fmaf(e, e, dd);
                        e = xv.y - cv.y; dd = fmaf(e, e, dd);
                        e = xv.z - cv.z; dd = fmaf(e, e, dd);
                        e = xv.w - cv.w; dd = fmaf(e, e, dd);
                    }
                    if (dd < bestd || (dd == bestd && cjj[c] < bidx)) { bestd = dd; bidx = cjj[c]; }
                }
            }
            dist = bestd;
        }
        out[(size_t)NROWS * D + myrow] = (float)bidx;
        lacc += dist;

        // ---- gather winners' exact fp32 codewords (quad-cooperative) ----
        #pragma unroll
        for (int rg = 0; rg < 4; rg++) {
            int w = __shfl_sync(0xffffffffu, bidx, (lane & ~3) + rg);
            const float4* c4p = reinterpret_cast<const float4*>(cwf + (size_t)w * D);
            float4* o = reinterpret_cast<float4*>(out + (size_t)(rowbase + rg * 8 + g) * D);
            #pragma unroll
            for (int j = 0; j < 4; j++) o[j * 4 + q] = c4p[j * 4 + q];
        }
    }

    // ---- loss: block reduce -> partial; last block finalizes ----
    #pragma unroll
    for (int off = 16; off; off >>= 1) lacc += __shfl_xor_sync(0xffffffffu, lacc, off);
    __shared__ float wred[8];
    if (lane == 0) wred[wid] = lacc;
    __syncthreads();
    if (tid == 0) {
        float s = 0.f;
        #pragma unroll
        for (int w = 0; w < 8; w++) s += wred[w];
        g_partial[blockIdx.x] = s;
        __threadfence();
        int ticket = atomicAdd(&g_counter, 1);
        if (ticket == grid - 1) {
            float tot = 0.f;
            for (int i = 0; i < grid; i++) tot += g_partial[i];
            out[(size_t)NROWS * D + NROWS] = 0.25f * tot / (float)((size_t)NROWS * D);
            g_counter = 0;   // reset for next graph replay
        }
    }
}

// ---------------- launch ----------------
extern "C" void kernel_launch(void* const* d_in, const int* in_sizes, int n_in,
                              void* d_out, int out_size) {
    const float* inputs    = (const float*)d_in[0];
    const float* codewords = (const float*)d_in[1];
    float* out = (float*)d_out;

    int sms = 148;
    cudaDeviceGetAttribute(&sms, cudaDevAttrMultiProcessorCount, 0);
    if (sms > NTILES) sms = NTILES;
    if (sms > 256)    sms = 256;

    cudaFuncSetAttribute(vq_main_kernel,
                         cudaFuncAttributeMaxDynamicSharedMemorySize, SM_TOTAL);

    vq_main_kernel<<<sms, 256, SM_TOTAL>>>(inputs, codewords, out, sms);
}